// round 1
// baseline (speedup 1.0000x reference)
#include <cuda_runtime.h>
#include <cstdint>

// Problem dims
#define B_    64
#define J_    1024
#define M_    256   // input feature dim (GEMM K)
#define NC_   32    // num capsules
#define DC_   32    // dim capsule
#define EPS_  1e-7f

// Scratch (device globals; no allocation allowed)
__device__ float g_xsum[B_ * M_];              // 64*256
__device__ float g_Wv  [B_ * NC_ * M_];        // 64*32*256
__device__ float g_c   [B_ * J_ * NC_];        // 64*1024*32 (coupling coeffs, [b][j][i])
__device__ float g_cx1 [B_ * NC_ * M_];
__device__ float g_cx2 [B_ * NC_ * M_];

// ---------- f32x2 helpers (sm_103a packed fp32 FMA) ----------
__device__ __forceinline__ unsigned long long pk2(float a, float b) {
    unsigned long long r;
    asm("mov.b64 %0, {%1,%2};" : "=l"(r) : "f"(a), "f"(b));
    return r;
}
__device__ __forceinline__ void upk2(unsigned long long v, float& a, float& b) {
    asm("mov.b64 {%0,%1}, %2;" : "=f"(a), "=f"(b) : "l"(v));
}
__device__ __forceinline__ unsigned long long ffma2(unsigned long long a,
                                                    unsigned long long b,
                                                    unsigned long long c) {
    unsigned long long d;
    asm("fma.rn.f32x2 %0, %1, %2, %3;" : "=l"(d) : "l"(a), "l"(b), "l"(c));
    return d;
}

// ---------- init: zero accumulated buffers ----------
__global__ void k_init() {
    int stride = gridDim.x * blockDim.x;
    for (int idx = blockIdx.x * blockDim.x + threadIdx.x; idx < B_ * NC_ * M_; idx += stride) {
        g_cx1[idx] = 0.f;
        g_cx2[idx] = 0.f;
        if (idx < B_ * M_) g_xsum[idx] = 0.f;
    }
}

// ---------- xsum[b,m] = sum_j x[b,j,m] ----------
__global__ void __launch_bounds__(256) k_xsum(const float* __restrict__ x) {
    int b = blockIdx.x, seg = blockIdx.y;     // grid (64, 8)
    int m = threadIdx.x;
    size_t base = ((size_t)b * J_ + seg * 128) * M_ + m;
    float s = 0.f;
#pragma unroll 8
    for (int j = 0; j < 128; ++j) s += x[base + (size_t)j * M_];
    atomicAdd(&g_xsum[b * M_ + m], s);
}

// ---------- caps: out = squash(inp @ W_i * scale); Wv = W_i @ out ----------
// MODE 0: inp = g_xsum (per-batch row), scale=1/32, write g_Wv
// MODE 1: inp = g_cx1, scale=1, write g_Wv
// MODE 2: inp = g_cx2, scale=1, write final out
template <int MODE>
__global__ void __launch_bounds__(256) k_caps(const float* __restrict__ W, float* __restrict__ out) {
    __shared__ float Wsh[M_ * 33];
    __shared__ float rowsh[M_];
    __shared__ float osh[NC_];
    int t = threadIdx.x;
    int bi = blockIdx.x;              // 0..2047
    int b = bi >> 5, i = bi & 31;

#pragma unroll 4
    for (int c = 0; c < 32; ++c) {
        int lin = t + 256 * c;        // 8192 elements
        int m = lin >> 5, k = lin & 31;
        Wsh[m * 33 + k] = W[m * (NC_ * DC_) + i * DC_ + k];
    }
    if (MODE == 0)      rowsh[t] = g_xsum[b * M_ + t];
    else if (MODE == 1) rowsh[t] = g_cx1[((size_t)b * NC_ + i) * M_ + t];
    else                rowsh[t] = g_cx2[((size_t)b * NC_ + i) * M_ + t];
    __syncthreads();

    if (t < 32) {
        float s = 0.f;
#pragma unroll 8
        for (int m = 0; m < M_; ++m) s += rowsh[m] * Wsh[m * 33 + t];
        float v = (MODE == 0) ? s * (1.0f / 32.0f) : s;
        float sq = v * v;
#pragma unroll
        for (int off = 16; off; off >>= 1) sq += __shfl_xor_sync(0xffffffffu, sq, off);
        float o = v / sqrtf(sq + EPS_);
        osh[t] = o;
        if (MODE == 2) out[((size_t)b * NC_ + i) * DC_ + t] = o;
    }
    __syncthreads();

    if (MODE != 2) {
        float wv = 0.f;
#pragma unroll
        for (int k = 0; k < 32; ++k) wv += Wsh[t * 33 + k] * osh[k];
        g_Wv[((size_t)b * NC_ + i) * M_ + t] = wv;
    }
}

// ---------- logits+softmax: c[b,j,i] = softmax_i( x[b,j,:] . Wv[b,i,:] ) ----------
// grid (64, 8); block 256 = 32(tx: j-lanes) x 8(ty: i-warps). 128 j per block.
// Micro-tile per thread: 4j x 4i, K packed as f32x2.
__global__ void __launch_bounds__(256) k_logits(const float* __restrict__ x) {
    extern __shared__ unsigned long long dsm[];
    unsigned long long* wvT = dsm;             // [128 k2][33 pad] -> idx k2*33+i  (4224)
    unsigned long long* xT  = dsm + 4224;      // [32 k2][129 pad] -> idx k2g*129+j (4128)
    float* b1sh = (float*)(dsm + 4224);        // reuse xT region: [128 j][33 pad]

    int t = threadIdx.x, tx = t & 31, ty = t >> 5;
    int b = blockIdx.x, j0 = blockIdx.y * 128;

    // stage Wv transposed+packed: wvT[k2][i] = (Wv[i][2k2], Wv[i][2k2+1])
    const float2* wv2g = (const float2*)(g_Wv + (size_t)b * NC_ * M_);
#pragma unroll 4
    for (int c = 0; c < 16; ++c) {
        int lin = t + 256 * c;                 // 4096 float2
        int k2 = lin & 127, i = lin >> 7;
        float2 w = wv2g[i * 128 + k2];
        wvT[k2 * 33 + i] = pk2(w.x, w.y);
    }

    unsigned long long acc[4][4] = {};         // [jj][ii]

    for (int kc = 0; kc < 4; ++kc) {           // K chunks of 64 floats (32 f2)
        __syncthreads();
#pragma unroll
        for (int c = 0; c < 8; ++c) {
            int lin = t + 256 * c;             // 2048 float4
            int j = lin >> 4, kq = lin & 15;
            float4 v = *(const float4*)(x + ((size_t)b * J_ + j0 + j) * M_ + kc * 64 + kq * 4);
            int k2 = kq * 2;
            xT[k2 * 129 + j]       = pk2(v.x, v.y);
            xT[(k2 + 1) * 129 + j] = pk2(v.z, v.w);
        }
        __syncthreads();
#pragma unroll 8
        for (int k2g = 0; k2g < 32; ++k2g) {
            unsigned long long xv[4], wv[4];
#pragma unroll
            for (int jj = 0; jj < 4; ++jj) xv[jj] = xT[k2g * 129 + tx + 32 * jj];
#pragma unroll
            for (int ii = 0; ii < 4; ++ii) wv[ii] = wvT[(kc * 32 + k2g) * 33 + ty + 8 * ii];
#pragma unroll
            for (int jj = 0; jj < 4; ++jj)
#pragma unroll
                for (int ii = 0; ii < 4; ++ii)
                    acc[jj][ii] = ffma2(xv[jj], wv[ii], acc[jj][ii]);
        }
    }
    __syncthreads();                           // xT reads done; reuse as b1sh
#pragma unroll
    for (int jj = 0; jj < 4; ++jj)
#pragma unroll
        for (int ii = 0; ii < 4; ++ii) {
            float lo, hi; upk2(acc[jj][ii], lo, hi);
            b1sh[(tx + 32 * jj) * 33 + ty + 8 * ii] = lo + hi;
        }
    __syncthreads();

    if (t < 128) {
        float* row = b1sh + t * 33;
        float mx = row[0];
#pragma unroll
        for (int i = 1; i < 32; ++i) mx = fmaxf(mx, row[i]);
        float s = 0.f;
#pragma unroll
        for (int i = 0; i < 32; ++i) { float e = __expf(row[i] - mx); row[i] = e; s += e; }
        float inv = 1.0f / s;
        float* cg = g_c + ((size_t)b * J_ + j0 + t) * NC_;
#pragma unroll
        for (int q = 0; q < 8; ++q) {
            float4 o;
            o.x = row[4 * q + 0] * inv; o.y = row[4 * q + 1] * inv;
            o.z = row[4 * q + 2] * inv; o.w = row[4 * q + 3] * inv;
            ((float4*)cg)[q] = o;
        }
    }
}

// ---------- cx accumulation: cx[b,i,m] += sum_j c[b,j,i] * x[b,j,m] ----------
// grid (64, 8); block 256 = 32(tx: m2-lanes) x 8(ty: i-warps). 128 j per block, atomic out.
// PASS 0 -> g_cx1, PASS 1 -> g_cx2
template <int PASS>
__global__ void __launch_bounds__(256) k_cx(const float* __restrict__ x) {
    __shared__ unsigned long long xsh[32 * 128]; // [32 j][128 m2]
    __shared__ float csh[32 * 33];               // [32 j][32 i pad]
    int t = threadIdx.x, tx = t & 31, ty = t >> 5;
    int b = blockIdx.x, j0 = blockIdx.y * 128;

    unsigned long long acc[4][4] = {};           // [ii][mm]

    for (int jc = 0; jc < 4; ++jc) {
        __syncthreads();
        int jb = j0 + jc * 32;
#pragma unroll
        for (int c = 0; c < 4; ++c) {
            int lin = t + 256 * c;               // 1024 floats
            int jj = lin >> 5, i = lin & 31;
            csh[jj * 33 + i] = g_c[((size_t)b * J_ + jb + jj) * NC_ + i];
        }
#pragma unroll
        for (int c = 0; c < 8; ++c) {
            int lin = t + 256 * c;               // 2048 float4
            int jj = lin >> 6, q = lin & 63;
            float4 v = *(const float4*)(x + ((size_t)b * J_ + jb + jj) * M_ + q * 4);
            xsh[jj * 128 + 2 * q]     = pk2(v.x, v.y);
            xsh[jj * 128 + 2 * q + 1] = pk2(v.z, v.w);
        }
        __syncthreads();
#pragma unroll 8
        for (int jj = 0; jj < 32; ++jj) {
            unsigned long long cc[4], xv[4];
#pragma unroll
            for (int ii = 0; ii < 4; ++ii) {
                float cv = csh[jj * 33 + ty + 8 * ii];
                cc[ii] = pk2(cv, cv);
            }
#pragma unroll
            for (int mm = 0; mm < 4; ++mm) xv[mm] = xsh[jj * 128 + tx + 32 * mm];
#pragma unroll
            for (int ii = 0; ii < 4; ++ii)
#pragma unroll
                for (int mm = 0; mm < 4; ++mm)
                    acc[ii][mm] = ffma2(xv[mm], cc[ii], acc[ii][mm]);
        }
    }

    float* cxo = (PASS == 0) ? g_cx1 : g_cx2;
#pragma unroll
    for (int ii = 0; ii < 4; ++ii)
#pragma unroll
        for (int mm = 0; mm < 4; ++mm) {
            float lo, hi; upk2(acc[ii][mm], lo, hi);
            size_t o = ((size_t)b * NC_ + ty + 8 * ii) * M_ + 2 * (tx + 32 * mm);
            atomicAdd(&cxo[o],     lo);
            atomicAdd(&cxo[o + 1], hi);
        }
}

extern "C" void kernel_launch(void* const* d_in, const int* in_sizes, int n_in,
                              void* d_out, int out_size) {
    const float* x = (const float*)d_in[0];
    const float* W = (const float*)d_in[1];
    if (n_in >= 2 && in_sizes[0] < in_sizes[1]) {   // safety: x is the big one
        const float* tmp = x; x = W; W = tmp;
    }
    float* out = (float*)d_out;

    cudaFuncSetAttribute(k_logits, cudaFuncAttributeMaxDynamicSharedMemorySize, 66816);

    k_init<<<1024, 512>>>();
    k_xsum<<<dim3(B_, 8), 256>>>(x);

    // iter 0: out0 from xsum, build Wv0
    k_caps<0><<<B_ * NC_, 256>>>(W, out);
    // iter 1
    k_logits<<<dim3(B_, 8), 256, 66816>>>(x);
    k_cx<0><<<dim3(B_, 8), 256>>>(x);
    k_caps<1><<<B_ * NC_, 256>>>(W, out);
    // iter 2 (final)
    k_logits<<<dim3(B_, 8), 256, 66816>>>(x);
    k_cx<1><<<dim3(B_, 8), 256>>>(x);
    k_caps<2><<<B_ * NC_, 256>>>(W, out);
}

// round 2
// speedup vs baseline: 1.1275x; 1.1275x over previous
#include <cuda_runtime.h>
#include <cstdint>

#define B_    64
#define J_    1024
#define M_    256
#define NC_   32
#define DC_   32
#define EPS_  1e-7f
#define SEG_  8      // j-segments (grid.y) for big kernels

// Scratch
__device__ float g_xsump[SEG_ * B_ * M_];
__device__ float g_Wv   [B_ * NC_ * M_];
__device__ float g_c    [B_ * J_ * NC_];
__device__ float g_cxp  [SEG_ * B_ * NC_ * M_];

// ---------- f32x2 helpers ----------
__device__ __forceinline__ unsigned long long pk2(float a, float b) {
    unsigned long long r;
    asm("mov.b64 %0, {%1,%2};" : "=l"(r) : "f"(a), "f"(b));
    return r;
}
__device__ __forceinline__ void upk2(unsigned long long v, float& a, float& b) {
    asm("mov.b64 {%0,%1}, %2;" : "=f"(a), "=f"(b) : "l"(v));
}
__device__ __forceinline__ unsigned long long ffma2(unsigned long long a,
                                                    unsigned long long b,
                                                    unsigned long long c) {
    unsigned long long d;
    asm("fma.rn.f32x2 %0, %1, %2, %3;" : "=l"(d) : "l"(a), "l"(b), "l"(c));
    return d;
}

// ---------- xsum partials ----------
__global__ void __launch_bounds__(256) k_xsum(const float* __restrict__ x) {
    int b = blockIdx.x, seg = blockIdx.y;
    int m = threadIdx.x;
    size_t base = ((size_t)b * J_ + seg * 128) * M_ + m;
    float s = 0.f;
#pragma unroll 8
    for (int j = 0; j < 128; ++j) s += x[base + (size_t)j * M_];
    g_xsump[((size_t)seg * B_ + b) * M_ + m] = s;
}

// ---------- caps: out = squash(row @ W_i); Wv = W_i @ out ----------
// grid (32 i, 16 bg), block 256, 4 batches per block.
// MODE 0: row = sum_seg xsump, scale 1/32, write Wv
// MODE 1: row = sum_seg cxp, write Wv
// MODE 2: row = sum_seg cxp, write final out
template <int MODE>
__global__ void __launch_bounds__(256) k_caps(const float* __restrict__ W, float* __restrict__ out) {
    __shared__ float Wsh[M_ * 33];
    __shared__ float rowsh[M_];
    __shared__ float psh[8 * 32];
    __shared__ float osh[NC_];
    int t = threadIdx.x;
    int i = blockIdx.x, bg = blockIdx.y;

#pragma unroll 4
    for (int c = 0; c < 32; ++c) {
        int lin = t + 256 * c;
        int m = lin >> 5, k = lin & 31;
        Wsh[m * 33 + k] = W[m * (NC_ * DC_) + i * DC_ + k];
    }

    for (int bb = 0; bb < 4; ++bb) {
        int b = bg * 4 + bb;
        float r = 0.f;
        if (MODE == 0) {
#pragma unroll
            for (int s = 0; s < SEG_; ++s) r += g_xsump[((size_t)s * B_ + b) * M_ + t];
        } else {
#pragma unroll
            for (int s = 0; s < SEG_; ++s)
                r += g_cxp[(((size_t)s * B_ + b) * NC_ + i) * M_ + t];
        }
        __syncthreads();
        rowsh[t] = r;
        __syncthreads();

        {   // partial dots: thread (k = t&31, g = t>>5) over 32 m
            int k = t & 31, g = t >> 5;
            float p = 0.f;
#pragma unroll 8
            for (int mm = 0; mm < 32; ++mm)
                p += rowsh[g * 32 + mm] * Wsh[(g * 32 + mm) * 33 + k];
            psh[g * 32 + k] = p;
        }
        __syncthreads();

        if (t < 32) {
            float s = 0.f;
#pragma unroll
            for (int g = 0; g < 8; ++g) s += psh[g * 32 + t];
            float v = (MODE == 0) ? s * (1.0f / 32.0f) : s;
            float sq = v * v;
#pragma unroll
            for (int off = 16; off; off >>= 1) sq += __shfl_xor_sync(0xffffffffu, sq, off);
            float o = v / sqrtf(sq + EPS_);
            osh[t] = o;
            if (MODE == 2) out[((size_t)b * NC_ + i) * DC_ + t] = o;
        }
        __syncthreads();

        if (MODE != 2) {
            float wv = 0.f;
#pragma unroll
            for (int k = 0; k < 32; ++k) wv += Wsh[t * 33 + k] * osh[k];
            g_Wv[((size_t)b * NC_ + i) * M_ + t] = wv;
        }
        __syncthreads();
    }
}

// ---------- logits + softmax ----------
// grid (64, 8), block 128 = 4 warps. Block tile: 128 j x 32 i, K = 256.
// Per-thread tile 4j x 8i; warp w owns i = w*8..w*8+7 (wv broadcast).
// smem: wvP [64 kq][33 pad] ulonglong2 (k2-pairs), xsh [128 j][17 pad] ulonglong2 per chunk.
__global__ void __launch_bounds__(128) k_logits(const float* __restrict__ x) {
    extern __shared__ char dyn[];
    ulonglong2* wvP = (ulonglong2*)dyn;                       // 64*33*16 = 33792 B
    ulonglong2* xsh = (ulonglong2*)(dyn + 33792);             // 128*17*16 = 34816 B
    float*      b1  = (float*)(dyn + 33792);                  // reuse xsh

    int t = threadIdx.x, tx = t & 31, w = t >> 5;
    int b = blockIdx.x, j0 = blockIdx.y * 128;

    // stage Wv as k2-pairs: wvP[kq][i] = {(m=4kq..), (m=4kq+2..)} packed
    const float4* wv4 = (const float4*)(g_Wv + (size_t)b * NC_ * M_);
#pragma unroll
    for (int c = 0; c < 16; ++c) {
        int lin = t + 128 * c;            // 2048 float4
        int i = lin >> 6, kq = lin & 63;
        float4 v = wv4[i * 64 + kq];
        ulonglong2 p; p.x = pk2(v.x, v.y); p.y = pk2(v.z, v.w);
        wvP[kq * 33 + i] = p;
    }

    unsigned long long acc[4][8] = {};    // [jj][ii]

    for (int kc = 0; kc < 4; ++kc) {      // 4 chunks x 16 kq (64 floats)
        __syncthreads();
#pragma unroll
        for (int c = 0; c < 16; ++c) {
            int lin = t + 128 * c;        // 2048 float4
            int j = lin >> 4, mq = lin & 15;
            float4 v = *(const float4*)(x + ((size_t)b * J_ + j0 + j) * M_ + kc * 64 + mq * 4);
            ulonglong2 p; p.x = pk2(v.x, v.y); p.y = pk2(v.z, v.w);
            xsh[j * 17 + mq] = p;
        }
        __syncthreads();
#pragma unroll 4
        for (int kq = 0; kq < 16; ++kq) {
            ulonglong2 xv[4], wv[8];
#pragma unroll
            for (int jj = 0; jj < 4; ++jj) xv[jj] = xsh[(tx + 32 * jj) * 17 + kq];
#pragma unroll
            for (int ii = 0; ii < 8; ++ii) wv[ii] = wvP[(kc * 16 + kq) * 33 + w * 8 + ii];
#pragma unroll
            for (int jj = 0; jj < 4; ++jj)
#pragma unroll
                for (int ii = 0; ii < 8; ++ii)
                    acc[jj][ii] = ffma2(xv[jj].y, wv[ii].y,
                                  ffma2(xv[jj].x, wv[ii].x, acc[jj][ii]));
        }
    }
    __syncthreads();                      // xsh reads done; reuse as b1
#pragma unroll
    for (int jj = 0; jj < 4; ++jj)
#pragma unroll
        for (int ii = 0; ii < 8; ++ii) {
            float lo, hi; upk2(acc[jj][ii], lo, hi);
            b1[(tx + 32 * jj) * 33 + w * 8 + ii] = lo + hi;
        }
    __syncthreads();

    {   // softmax over i per j; t = j (128 threads)
        float* row = b1 + t * 33;
        float mx = row[0];
#pragma unroll
        for (int i = 1; i < 32; ++i) mx = fmaxf(mx, row[i]);
        float s = 0.f;
#pragma unroll
        for (int i = 0; i < 32; ++i) { float e = __expf(row[i] - mx); row[i] = e; s += e; }
        float inv = 1.0f / s;
        float* cg = g_c + ((size_t)b * J_ + j0 + t) * NC_;
#pragma unroll
        for (int q = 0; q < 8; ++q) {
            float4 o;
            o.x = row[4 * q + 0] * inv; o.y = row[4 * q + 1] * inv;
            o.z = row[4 * q + 2] * inv; o.w = row[4 * q + 3] * inv;
            ((float4*)cg)[q] = o;
        }
    }
}

// ---------- cx partials: cxp[seg][b][i][m] = sum_{j in seg} c[b][j][i] * x[b][j][m] ----------
// grid (64, 8), block 128 = 4 warps. Per-thread tile 8i x 4m2; warp w owns i = w*8..+7.
__global__ void __launch_bounds__(128) k_cx(const float* __restrict__ x) {
    __shared__ ulonglong2 xsh[32 * 64];   // [32 j][64 ull2 = 128 m2]  32 KB
    __shared__ float      csh[32 * 32];   // [32 j][32 i]               4 KB
    int t = threadIdx.x, tx = t & 31, w = t >> 5;
    int b = blockIdx.x, seg = blockIdx.y, j0 = seg * 128;

    const unsigned long long* xshu = (const unsigned long long*)xsh;
    const float4* csh4v = (const float4*)csh;

    unsigned long long acc[8][4] = {};    // [ii][mm]

    for (int jc = 0; jc < 4; ++jc) {
        __syncthreads();
        int jb = j0 + jc * 32;
#pragma unroll
        for (int c = 0; c < 16; ++c) {
            int lin = t + 128 * c;        // 2048 float4
            int j = lin >> 6, mq = lin & 63;
            float4 v = *(const float4*)(x + ((size_t)b * J_ + jb + j) * M_ + mq * 4);
            ulonglong2 p; p.x = pk2(v.x, v.y); p.y = pk2(v.z, v.w);
            xsh[j * 64 + mq] = p;
        }
#pragma unroll
        for (int c = 0; c < 2; ++c) {
            int lin = t + 128 * c;        // 256 float4
            int j = lin >> 3, q = lin & 7;
            float4 v = *(const float4*)(g_c + ((size_t)b * J_ + jb + j) * NC_ + q * 4);
            ((float4*)csh)[j * 8 + q] = v;
        }
        __syncthreads();
#pragma unroll 4
        for (int j = 0; j < 32; ++j) {
            float4 ca = csh4v[j * 8 + w * 2];
            float4 cb = csh4v[j * 8 + w * 2 + 1];
            unsigned long long cc[8];
            cc[0] = pk2(ca.x, ca.x); cc[1] = pk2(ca.y, ca.y);
            cc[2] = pk2(ca.z, ca.z); cc[3] = pk2(ca.w, ca.w);
            cc[4] = pk2(cb.x, cb.x); cc[5] = pk2(cb.y, cb.y);
            cc[6] = pk2(cb.z, cb.z); cc[7] = pk2(cb.w, cb.w);
            unsigned long long xv[4];
#pragma unroll
            for (int mm = 0; mm < 4; ++mm) xv[mm] = xshu[j * 128 + tx + 32 * mm];
#pragma unroll
            for (int ii = 0; ii < 8; ++ii)
#pragma unroll
                for (int mm = 0; mm < 4; ++mm)
                    acc[ii][mm] = ffma2(xv[mm], cc[ii], acc[ii][mm]);
        }
    }

    // write partial slab (no atomics)
#pragma unroll
    for (int ii = 0; ii < 8; ++ii)
#pragma unroll
        for (int mm = 0; mm < 4; ++mm) {
            float lo, hi; upk2(acc[ii][mm], lo, hi);
            size_t o = (((size_t)seg * B_ + b) * NC_ + w * 8 + ii) * M_ + 2 * (tx + 32 * mm);
            float2 v; v.x = lo; v.y = hi;
            *(float2*)(g_cxp + o) = v;
        }
}

extern "C" void kernel_launch(void* const* d_in, const int* in_sizes, int n_in,
                              void* d_out, int out_size) {
    const float* x = (const float*)d_in[0];
    const float* W = (const float*)d_in[1];
    if (n_in >= 2 && in_sizes[0] < in_sizes[1]) {
        const float* tmp = x; x = W; W = tmp;
    }
    float* out = (float*)d_out;

    cudaFuncSetAttribute(k_logits, cudaFuncAttributeMaxDynamicSharedMemorySize, 68608);

    k_xsum<<<dim3(B_, SEG_), 256>>>(x);
    k_caps<0><<<dim3(NC_, 16), 256>>>(W, out);

    k_logits<<<dim3(B_, SEG_), 128, 68608>>>(x);
    k_cx<<<dim3(B_, SEG_), 128>>>(x);
    k_caps<1><<<dim3(NC_, 16), 256>>>(W, out);

    k_logits<<<dim3(B_, SEG_), 128, 68608>>>(x);
    k_cx<<<dim3(B_, SEG_), 128>>>(x);
    k_caps<2><<<dim3(NC_, 16), 256>>>(W, out);
}